// round 6
// baseline (speedup 1.0000x reference)
#include <cuda_runtime.h>

// Involution: B=4, H=W=56, C=256, Cr=64, G=16, Cg=16, K=7, pad=3
// Round 5: warp-specialized inv_main (B3 producer / B4 consumer, double-buffered
// kg, named-barrier handshake), coalesced prep transpose, BN folded into rs.

#define HH 56
#define WWD 56
#define CC 256
#define CR 64
#define NG 16
#define CGC 16
#define KKT 49
#define NPIXT 12544
#define HALO_W 14
#define NPOS 140
#define XHP 24
#define KGPAD 50
#define RSP 68

__device__ __align__(16) float g_wsT[NG * KKT * CR];   // [g*49+k][d]
__device__ __align__(16) float g_rs[(size_t)NPIXT * CR];

#define BAR_SYNC_256(id)   asm volatile("bar.sync %0, 256;"   :: "r"(id) : "memory")
#define BAR_ARRIVE_256(id) asm volatile("bar.arrive %0, 256;" :: "r"(id) : "memory")
#define MEMBAR_CTA()       asm volatile("membar.cta;" ::: "memory")

// ---------------------------------------------------------------- prep: transpose w_span
__global__ void prep_kernel(const float* __restrict__ wspan) {
    __shared__ float tile[32][33];
    const int tx = threadIdx.x & 31, ty8 = threadIdx.x >> 5;  // 256 thr: 32x8
    const int gk0 = blockIdx.x * 32, d0 = blockIdx.y * 32;
    #pragma unroll
    for (int r = 0; r < 32; r += 8) {
        int d = d0 + ty8 + r, gk = gk0 + tx;
        tile[ty8 + r][tx] = (gk < KKT * NG) ? wspan[(size_t)d * (KKT * NG) + gk] : 0.f;
    }
    __syncthreads();
    #pragma unroll
    for (int r = 0; r < 32; r += 8) {
        int gk = gk0 + ty8 + r, d = d0 + tx;
        if (gk < KKT * NG) g_wsT[(size_t)gk * CR + d] = tile[tx][ty8 + r];
    }
}

// ---------------------------------------------------------------- rs GEMM (BN folded in epilogue)
#define RPX 128
struct SmemR {
    float xs[RPX][68];
    float ws[CR][CR];
};

__global__ __launch_bounds__(256)
void rs_kernel(const float* __restrict__ x,
               const float* __restrict__ wr,
               const float* __restrict__ gamma,
               const float* __restrict__ beta,
               const float* __restrict__ mean,
               const float* __restrict__ var) {
    extern __shared__ __align__(16) float smr[];
    SmemR& s = *reinterpret_cast<SmemR*>(smr);
    const int t = threadIdx.x;
    const int pix0 = blockIdx.x * RPX;
    const int dt = t & 15, mt = t >> 4;
    const int d0 = dt * 4;

    float4 acc[8];
    #pragma unroll
    for (int i = 0; i < 8; ++i) acc[i] = make_float4(0.f, 0.f, 0.f, 0.f);

    for (int cb = 0; cb < 4; ++cb) {
        for (int i = t; i < RPX * 16; i += 256) {
            int p = i >> 4, c = i & 15;
            *(float4*)&s.xs[p][c * 4] =
                __ldg((const float4*)&x[(size_t)(pix0 + p) * CC + cb * 64 + c * 4]);
        }
        for (int i = t; i < 64 * 16; i += 256) {
            int r = i >> 4, c = i & 15;
            *(float4*)&s.ws[r][c * 4] =
                __ldg((const float4*)&wr[(size_t)(cb * 64 + r) * CR + c * 4]);
        }
        __syncthreads();
        #pragma unroll 4
        for (int c4 = 0; c4 < 16; ++c4) {
            float4 w0 = *(float4*)&s.ws[c4 * 4 + 0][d0];
            float4 w1 = *(float4*)&s.ws[c4 * 4 + 1][d0];
            float4 w2 = *(float4*)&s.ws[c4 * 4 + 2][d0];
            float4 w3 = *(float4*)&s.ws[c4 * 4 + 3][d0];
            #pragma unroll
            for (int i = 0; i < 8; ++i) {
                float4 a = *(float4*)&s.xs[mt * 8 + i][c4 * 4];
                acc[i].x += a.x*w0.x + a.y*w1.x + a.z*w2.x + a.w*w3.x;
                acc[i].y += a.x*w0.y + a.y*w1.y + a.z*w2.y + a.w*w3.y;
                acc[i].z += a.x*w0.z + a.y*w1.z + a.z*w2.z + a.w*w3.z;
                acc[i].w += a.x*w0.w + a.y*w1.w + a.z*w2.w + a.w*w3.w;
            }
        }
        __syncthreads();
    }
    // BN fold: y = relu(acc * s + (beta - mean * s)),  s = gamma * rsqrt(var+eps)
    float4 gm = __ldg((const float4*)&gamma[d0]);
    float4 bt = __ldg((const float4*)&beta[d0]);
    float4 mn = __ldg((const float4*)&mean[d0]);
    float4 vr = __ldg((const float4*)&var[d0]);
    float4 sc, bb2;
    sc.x = gm.x * rsqrtf(vr.x + 1e-3f); bb2.x = bt.x - mn.x * sc.x;
    sc.y = gm.y * rsqrtf(vr.y + 1e-3f); bb2.y = bt.y - mn.y * sc.y;
    sc.z = gm.z * rsqrtf(vr.z + 1e-3f); bb2.z = bt.z - mn.z * sc.z;
    sc.w = gm.w * rsqrtf(vr.w + 1e-3f); bb2.w = bt.w - mn.w * sc.w;
    #pragma unroll
    for (int i = 0; i < 8; ++i) {
        float4 v;
        v.x = fmaxf(acc[i].x * sc.x + bb2.x, 0.f);
        v.y = fmaxf(acc[i].y * sc.y + bb2.y, 0.f);
        v.z = fmaxf(acc[i].z * sc.z + bb2.z, 0.f);
        v.w = fmaxf(acc[i].w * sc.w + bb2.w, 0.f);
        *(float4*)&g_rs[(size_t)(pix0 + mt * 8 + i) * CR + d0] = v;
    }
}

// ---------------------------------------------------------------- main (warp-specialized)
struct SmemM {
    float rs[32][RSP];            //  8704 B
    float xh[2][2][NPOS][XHP];    // 53760 B  double-buffered halos (2 groups each)
    float kg[2][2][32][KGPAD];    // 25600 B  double-buffered kernels (2 groups each)
};                                // 88064 B

// barrier ids: 1,2 = kg(buf) ready ; 3,4 = kg(buf) free
#define BID_READY(b) (1 + (b))
#define BID_FREE(b)  (3 + (b))

__device__ __forceinline__ void halo_load(SmemM& s, const float* __restrict__ x,
                                          int gA, int buf, int tl, int nthr,
                                          int h0, int w0, int bb) {
    for (int i = tl; i < 2 * NPOS * 4; i += nthr) {
        int g = i / (NPOS * 4);
        int rem = i - g * (NPOS * 4);
        int pos = rem >> 2, q = rem & 3;
        int hh = pos / HALO_W, ww = pos - hh * HALO_W;
        int h = h0 + hh - 3, w = w0 + ww - 3;
        float4 v = make_float4(0.f, 0.f, 0.f, 0.f);
        if (h >= 0 && h < HH && w >= 0 && w < WWD)
            v = __ldg((const float4*)&x[(((size_t)bb * HH + h) * WWD + w) * CC
                                        + (gA + g) * CGC + q * 4]);
        *(float4*)&s.xh[buf][g][pos][q * 4] = v;
    }
}

__global__ __launch_bounds__(256, 2)
void inv_main(const float* __restrict__ x,
              const float* __restrict__ b_span,
              float* __restrict__ out) {
    extern __shared__ __align__(16) float smf[];
    SmemM& s = *reinterpret_cast<SmemM*>(smf);
    const int t = threadIdx.x;
    const int w0 = blockIdx.x * 8, h0 = blockIdx.y * 4, bb = blockIdx.z;
    const size_t pixbase = ((size_t)bb * HH + h0) * WWD + w0;

    // prologue: stage rs tile + halo(0), all threads
    for (int i = t; i < 512; i += 256) {
        int p = i >> 4, c = i & 15;
        int py = p >> 3, pxl = p & 7;
        size_t pix = pixbase + (size_t)py * WWD + pxl;
        *(float4*)&s.rs[p][c * 4] = __ldg((const float4*)&g_rs[pix * CR + c * 4]);
    }
    halo_load(s, x, 0, 0, t, 256, h0, w0, bb);
    __syncthreads();

    if (t < 128) {
        // ---------------- PRODUCER: B3 span-GEMM into kg[buf] ----------------
        const int g = (t < 112) ? (t / 56) : 0;
        const int r = (t < 112) ? (t - g * 56) : 0;
        const int quad = r & 7, kgi = r >> 3;
        const int k0 = kgi * 7;
        for (int gp = 0; gp < 8; ++gp) {
            const int buf = gp & 1;
            const int gA = gp * 2;
            if (gp >= 2) BAR_SYNC_256(BID_FREE(buf));   // wait consumer freed buf
            if (t < 112) {
                const float* wrow = &g_wsT[(size_t)((gA + g) * KKT + k0) * CR];
                float acc[4][7];
                #pragma unroll
                for (int j = 0; j < 7; ++j) {
                    float bv = __ldg(&b_span[(gA + g) * KKT + k0 + j]);
                    acc[0][j] = bv; acc[1][j] = bv; acc[2][j] = bv; acc[3][j] = bv;
                }
                #pragma unroll 2
                for (int d4 = 0; d4 < 16; ++d4) {
                    float4 ra0 = *(float4*)&s.rs[quad +  0][d4 * 4];
                    float4 ra1 = *(float4*)&s.rs[quad +  8][d4 * 4];
                    float4 ra2 = *(float4*)&s.rs[quad + 16][d4 * 4];
                    float4 ra3 = *(float4*)&s.rs[quad + 24][d4 * 4];
                    #pragma unroll
                    for (int j = 0; j < 7; ++j) {
                        float4 w4 = __ldg((const float4*)&wrow[j * CR + d4 * 4]);
                        acc[0][j] += ra0.x*w4.x + ra0.y*w4.y + ra0.z*w4.z + ra0.w*w4.w;
                        acc[1][j] += ra1.x*w4.x + ra1.y*w4.y + ra1.z*w4.z + ra1.w*w4.w;
                        acc[2][j] += ra2.x*w4.x + ra2.y*w4.y + ra2.z*w4.z + ra2.w*w4.w;
                        acc[3][j] += ra3.x*w4.x + ra3.y*w4.y + ra3.z*w4.z + ra3.w*w4.w;
                    }
                }
                #pragma unroll
                for (int i = 0; i < 4; ++i)
                    #pragma unroll
                    for (int j = 0; j < 7; ++j)
                        s.kg[buf][g][quad + 8 * i][k0 + j] = acc[i][j];
            }
            MEMBAR_CTA();
            BAR_ARRIVE_256(BID_READY(buf));             // kg(gp) published
        }
    } else {
        // ---------------- CONSUMER: B4 involution + halo prefetch ----------------
        const int t2 = t - 128;
        const int g = t2 >> 6, r = t2 & 63;
        const int pp = r >> 2, c4 = r & 3;
        const int px0 = pp * 2, py = px0 >> 3, pxl = px0 & 7;
        for (int gp = 0; gp < 8; ++gp) {
            const int buf = gp & 1;
            const int gA = gp * 2;
            BAR_SYNC_256(BID_READY(buf));               // kg(gp) ready (also orders
                                                        // consumer halo STS from gp-1)
            {
                float4 a0 = make_float4(0.f, 0.f, 0.f, 0.f);
                float4 a1 = make_float4(0.f, 0.f, 0.f, 0.f);
                #pragma unroll
                for (int kh = 0; kh < 7; ++kh) {
                    float4 xw[8];
                    const int rb = (py + kh) * HALO_W + pxl;
                    #pragma unroll
                    for (int cc = 0; cc < 8; ++cc)
                        xw[cc] = *(float4*)&s.xh[buf][g][rb + cc][c4 * 4];
                    #pragma unroll
                    for (int kw = 0; kw < 7; ++kw) {
                        float k0v = s.kg[buf][g][px0][kh * 7 + kw];
                        float k1v = s.kg[buf][g][px0 + 1][kh * 7 + kw];
                        a0.x += k0v * xw[kw].x;     a0.y += k0v * xw[kw].y;
                        a0.z += k0v * xw[kw].z;     a0.w += k0v * xw[kw].w;
                        a1.x += k1v * xw[kw + 1].x; a1.y += k1v * xw[kw + 1].y;
                        a1.z += k1v * xw[kw + 1].z; a1.w += k1v * xw[kw + 1].w;
                    }
                }
                size_t o = (pixbase + (size_t)py * WWD + pxl) * CC + (gA + g) * CGC + c4 * 4;
                *(float4*)&out[o] = a0;
                *(float4*)&out[o + CC] = a1;
            }
            MEMBAR_CTA();
            BAR_ARRIVE_256(BID_FREE(buf));              // kg buf free for producer
            if (gp < 7)                                 // prefetch halo(gp+1)
                halo_load(s, x, gA + 2, (gp + 1) & 1, t2, 128, h0, w0, bb);
        }
    }
}

// ---------------------------------------------------------------- launch
extern "C" void kernel_launch(void* const* d_in, const int* in_sizes, int n_in,
                              void* d_out, int out_size) {
    (void)in_sizes; (void)n_in; (void)out_size;
    const float* x        = (const float*)d_in[0];
    const float* w_reduce = (const float*)d_in[1];
    const float* gamma    = (const float*)d_in[2];
    const float* beta     = (const float*)d_in[3];
    const float* mean     = (const float*)d_in[4];
    const float* var      = (const float*)d_in[5];
    const float* w_span   = (const float*)d_in[6];
    const float* b_span   = (const float*)d_in[7];
    float* out = (float*)d_out;

    cudaFuncSetAttribute(rs_kernel, cudaFuncAttributeMaxDynamicSharedMemorySize,
                         (int)sizeof(SmemR));
    cudaFuncSetAttribute(inv_main, cudaFuncAttributeMaxDynamicSharedMemorySize,
                         (int)sizeof(SmemM));

    dim3 pgrid((KKT * NG + 31) / 32, 2);
    prep_kernel<<<pgrid, 256>>>(w_span);
    rs_kernel<<<NPIXT / RPX, 256, sizeof(SmemR)>>>(x, w_reduce, gamma, beta, mean, var);
    dim3 grid(WWD / 8, HH / 4, 4);
    inv_main<<<grid, 256, sizeof(SmemM)>>>(x, b_span, out);
}